// round 13
// baseline (speedup 1.0000x reference)
#include <cuda_runtime.h>
#include <math.h>
#include <stdint.h>

#define B_    4
#define S_    512
#define D_    512
#define H_    8
#define DH_   64
#define MEM_  512
#define CMEM_ 128
#define KV_   1152
#define LLAT_ 256
#define FF_   2048
#define NL_   4

// ------------------------- scratch (device globals) -------------------------
__device__ float g_x   [B_*S_*D_];
__device__ float g_a   [B_*S_*D_];
__device__ float g_kv  [B_*KV_*D_];
__device__ float g_q   [B_*S_*D_];
__device__ float g_q2  [B_*S_*D_];
__device__ float g_kvp [2*B_*KV_*D_];
__device__ float g_dots[B_*H_*S_*KV_];
__device__ float g_pd  [B_*H_*S_*KV_];
__device__ float g_ctx [B_*S_*D_];
__device__ float g_packw[(4*D_)*D_];
__device__ float g_newcm[B_*CMEM_*D_];
__device__ float g_tb  [2*B_*MEM_*D_];
__device__ float g_cb  [2*B_*CMEM_*D_];
__device__ float g_lkv [2*B_*LLAT_*D_];
__device__ float g_d2  [B_*H_*S_*MEM_];
__device__ float g_d3  [B_*H_*S_*CMEM_];
__device__ float g_dx  [B_*H_*S_*LLAT_];
__device__ float g_ctxt[B_*S_*D_];
__device__ float g_ctxc[B_*S_*D_];
__device__ float g_y   [B_*S_*D_];
__device__ float g_h1  [B_*S_*FF_];
__device__ float g_loss[1];

// ------------------------- TF32 helpers -------------------------------------
__device__ __forceinline__ uint32_t f2tf(float x) {
    uint32_t r;
    asm("cvt.rna.tf32.f32 %0, %1;" : "=r"(r) : "f"(x));
    return r;
}
__device__ __forceinline__ void split3(float x, float& h, float& l) {
    uint32_t u = f2tf(x);
    h = __uint_as_float(u);
    l = __uint_as_float(f2tf(x - h));
}

__device__ __forceinline__ void mma8(float c[4], const uint32_t a[4], const uint32_t b[2]) {
    asm volatile(
        "mma.sync.aligned.m16n8k8.row.col.f32.tf32.tf32.f32 "
        "{%0,%1,%2,%3},{%4,%5,%6,%7},{%8,%9},{%0,%1,%2,%3};\n"
        : "+f"(c[0]), "+f"(c[1]), "+f"(c[2]), "+f"(c[3])
        : "r"(a[0]), "r"(a[1]), "r"(a[2]), "r"(a[3]), "r"(b[0]), "r"(b[1]));
}

// ------------------------- 3xTF32 tensor-core GEMM --------------------------
// Identical math/layout to R4/R6; producers rewritten for conflict-free STS.128.
// smem layout: [plane hi/lo][row m or n (64)][k (32, padded to 36)].
// Row stride 36 floats = 144 B (16B-aligned); STS.128 per-phase bank-groups
// (m + k/4) mod 8 are distinct -> conflict-free.
#define SST 36
template<bool TB, bool GELU>
__global__ void __launch_bounds__(128) gemm_t(
    const float* __restrict__ A, const float* __restrict__ Bm,
    float* __restrict__ C, const float* __restrict__ bias,
    const float* __restrict__ Res,
    int K, int lda, int ldb, int ldc, float alpha,
    int Hdiv, long sAb, long sAh, long sBb, long sBh, long sCb, long sCh)
{
    const int z  = blockIdx.z;
    const int bi = z / Hdiv, hi = z - bi * Hdiv;
    A  += (long)bi*sAb + (long)hi*sAh;
    Bm += (long)bi*sBb + (long)hi*sBh;
    C  += (long)bi*sCb + (long)hi*sCh;

    const int m0 = blockIdx.y * 64;
    const int n0 = blockIdx.x * 64;

    __shared__ __align__(16) float As[2][64][SST];
    __shared__ __align__(16) float Bs[2][64][SST];

    const int t    = threadIdx.x;
    const int warp = t >> 5;
    const int lane = t & 31;
    const int wm = (warp & 1) * 32;
    const int wn = (warp >> 1) * 32;
    const int group = lane >> 2;
    const int tig   = lane & 3;

    float c[2][4][4];
#pragma unroll
    for (int mt = 0; mt < 2; mt++)
#pragma unroll
        for (int nt = 0; nt < 4; nt++)
#pragma unroll
            for (int r = 0; r < 4; r++) c[mt][nt][r] = 0.f;

    for (int k0 = 0; k0 < K; k0 += 32) {
        // ---- A tile: float4 load, split, two STS.128 (conflict-free) ----
#pragma unroll
        for (int p = 0; p < 4; p++) {
            const int m = (t >> 3) + p * 16;
            const int k = (t & 7) << 2;
            float4 v = *(const float4*)(A + (long)(m0 + m) * lda + k0 + k);
            float4 h, l;
            split3(v.x, h.x, l.x); split3(v.y, h.y, l.y);
            split3(v.z, h.z, l.z); split3(v.w, h.w, l.w);
            *(float4*)&As[0][m][k] = h;
            *(float4*)&As[1][m][k] = l;
        }
        if (TB) {
            // B is [N,K] row-major: same pattern as A
#pragma unroll
            for (int p = 0; p < 4; p++) {
                const int n = (t >> 3) + p * 16;
                const int k = (t & 7) << 2;
                float4 v = *(const float4*)(Bm + (long)(n0 + n) * ldb + k0 + k);
                float4 h, l;
                split3(v.x, h.x, l.x); split3(v.y, h.y, l.y);
                split3(v.z, h.z, l.z); split3(v.w, h.w, l.w);
                *(float4*)&Bs[0][n][k] = h;
                *(float4*)&Bs[1][n][k] = l;
            }
        } else {
            // B is [K,N] row-major: 16 coalesced LDG.32 along k per thread
            // (lanes walk n), then STS.128 along the thread's own [n][k] row.
            const int n  = t & 63;
            const int kb = (t >> 6) << 4;     // 0 or 16
            const float* bp = Bm + (long)(k0 + kb) * ldb + n0 + n;
            float v[16];
#pragma unroll
            for (int i = 0; i < 16; i++) v[i] = bp[(long)i * ldb];
#pragma unroll
            for (int q = 0; q < 4; q++) {
                float4 h, l;
                split3(v[4*q+0], h.x, l.x); split3(v[4*q+1], h.y, l.y);
                split3(v[4*q+2], h.z, l.z); split3(v[4*q+3], h.w, l.w);
                *(float4*)&Bs[0][n][kb + 4*q] = h;
                *(float4*)&Bs[1][n][kb + 4*q] = l;
            }
        }
        __syncthreads();

#pragma unroll
        for (int kk = 0; kk < 32; kk += 8) {
            uint32_t ah[2][4], al[2][4], bh[4][2], bl[4][2];
#pragma unroll
            for (int mt = 0; mt < 2; mt++) {
                const int r0 = wm + mt * 16 + group;
                ah[mt][0] = __float_as_uint(As[0][r0    ][kk + tig]);
                ah[mt][1] = __float_as_uint(As[0][r0 + 8][kk + tig]);
                ah[mt][2] = __float_as_uint(As[0][r0    ][kk + tig + 4]);
                ah[mt][3] = __float_as_uint(As[0][r0 + 8][kk + tig + 4]);
                al[mt][0] = __float_as_uint(As[1][r0    ][kk + tig]);
                al[mt][1] = __float_as_uint(As[1][r0 + 8][kk + tig]);
                al[mt][2] = __float_as_uint(As[1][r0    ][kk + tig + 4]);
                al[mt][3] = __float_as_uint(As[1][r0 + 8][kk + tig + 4]);
            }
#pragma unroll
            for (int nt = 0; nt < 4; nt++) {
                const int nr = wn + nt * 8 + group;
                bh[nt][0] = __float_as_uint(Bs[0][nr][kk + tig]);
                bh[nt][1] = __float_as_uint(Bs[0][nr][kk + tig + 4]);
                bl[nt][0] = __float_as_uint(Bs[1][nr][kk + tig]);
                bl[nt][1] = __float_as_uint(Bs[1][nr][kk + tig + 4]);
            }
#pragma unroll
            for (int mt = 0; mt < 2; mt++)
#pragma unroll
                for (int nt = 0; nt < 4; nt++) {
                    mma8(c[mt][nt], al[mt], bh[nt]);
                    mma8(c[mt][nt], ah[mt], bl[nt]);
                    mma8(c[mt][nt], ah[mt], bh[nt]);
                }
        }
        __syncthreads();
    }

#pragma unroll
    for (int mt = 0; mt < 2; mt++) {
#pragma unroll
        for (int half = 0; half < 2; half++) {
            const int gm = m0 + wm + mt * 16 + group + half * 8;
            float* crow = C + (long)gm * ldc;
            const float* rrow = Res ? (Res + (long)gm * ldc) : nullptr;
#pragma unroll
            for (int nt = 0; nt < 4; nt++) {
                const int gn = n0 + wn + nt * 8 + 2 * tig;
                float v0 = alpha * c[mt][nt][half * 2 + 0];
                float v1 = alpha * c[mt][nt][half * 2 + 1];
                if (bias) {
                    float2 bv = *(const float2*)&bias[gn];
                    v0 += bv.x; v1 += bv.y;
                }
                if (GELU) {
                    v0 = 0.5f * v0 * (1.f + erff(v0 * 0.70710678118654752f));
                    v1 = 0.5f * v1 * (1.f + erff(v1 * 0.70710678118654752f));
                }
                if (rrow) {
                    float2 rv = *(const float2*)&rrow[gn];
                    v0 += rv.x; v1 += rv.y;
                }
                *(float2*)&crow[gn] = make_float2(v0, v1);
            }
        }
    }
}

// ------------------------- elementwise / reduction kernels ------------------
__global__ void embed_k(const int* __restrict__ trg, const float* __restrict__ embed)
{
    int idx = blockIdx.x * blockDim.x + threadIdx.x;
    if (idx >= B_*S_*D_) return;
    int row = idx / D_;
    g_x[idx] = embed[(long)trg[row]*D_ + (idx % D_)];
}

__global__ void concat_kv_k(const float* __restrict__ cm, const float* __restrict__ m)
{
    int idx = blockIdx.x * blockDim.x + threadIdx.x;
    if (idx >= B_*KV_*D_) return;
    int d = idx % D_;
    int j = (idx / D_) % KV_;
    int b = idx / (D_*KV_);
    float v;
    if (j < CMEM_)             v = cm [((long)b*CMEM_ + j)*D_ + d];
    else if (j < CMEM_ + MEM_) v = m  [((long)b*MEM_ + (j - CMEM_))*D_ + d];
    else                       v = g_x[((long)b*S_  + (j - CMEM_ - MEM_))*D_ + d];
    g_kv[idx] = v;
}

__global__ void softmax_pos_k()
{
    const long row = blockIdx.x;
    const int  q   = (int)(row % S_);
    float* dp = g_dots + row * (long)KV_;
    const float* pp = g_pd + row * (long)KV_;
    const int t = threadIdx.x;

    float v[5];
    float m = -1e30f;
#pragma unroll
    for (int r = 0; r < 5; r++) {
        int i = t + 256*r;
        if (i < KV_) {
            float val = dp[i];
            int p = i - q + (S_ - 1);
            if (p < KV_) val += pp[p];
            v[r] = val;
            m = fmaxf(m, val);
        } else v[r] = -1e30f;
    }
    __shared__ float red[256];
    red[t] = m; __syncthreads();
    for (int st = 128; st > 0; st >>= 1) { if (t < st) red[t] = fmaxf(red[t], red[t+st]); __syncthreads(); }
    m = red[0]; __syncthreads();
    float s = 0.f;
#pragma unroll
    for (int r = 0; r < 5; r++) {
        int i = t + 256*r;
        if (i < KV_) { v[r] = expf(v[r] - m); s += v[r]; }
    }
    red[t] = s; __syncthreads();
    for (int st = 128; st > 0; st >>= 1) { if (t < st) red[t] += red[t+st]; __syncthreads(); }
    float inv = 1.f / red[0];
#pragma unroll
    for (int r = 0; r < 5; r++) {
        int i = t + 256*r;
        if (i < KV_) dp[i] = v[r] * inv;
    }
}

__global__ void softmax_k(float* __restrict__ d, int L)
{
    long row = blockIdx.x;
    float* p = d + row * (long)L;
    const int t = threadIdx.x;
    float v[5];
    float m = -1e30f;
    const int nr = (L + 255) >> 8;
    for (int r = 0; r < nr; r++) {
        int i = t + 256*r;
        v[r] = (i < L) ? p[i] : -1e30f;
        m = fmaxf(m, v[r]);
    }
    __shared__ float red[256];
    red[t] = m; __syncthreads();
    for (int st = 128; st > 0; st >>= 1) { if (t < st) red[t] = fmaxf(red[t], red[t+st]); __syncthreads(); }
    m = red[0]; __syncthreads();
    float s = 0.f;
    for (int r = 0; r < nr; r++) {
        int i = t + 256*r;
        if (i < L) { v[r] = expf(v[r] - m); s += v[r]; }
    }
    red[t] = s; __syncthreads();
    for (int st = 128; st > 0; st >>= 1) { if (t < st) red[t] += red[t+st]; __syncthreads(); }
    float inv = 1.f / red[0];
    for (int r = 0; r < nr; r++) {
        int i = t + 256*r;
        if (i < L) p[i] = v[r] * inv;
    }
}

__global__ void ln_k(const float* __restrict__ in, const float* __restrict__ res,
                     float* __restrict__ out, const float* __restrict__ g,
                     const float* __restrict__ bta)
{
    long row = blockIdx.x;
    const float* p = in + row * D_;
    int t = threadIdx.x;
    float v0 = p[t]       + (res ? res[row*D_ + t]       : 0.f);
    float v1 = p[t + 256] + (res ? res[row*D_ + t + 256] : 0.f);
    __shared__ float s1[256], s2[256];
    s1[t] = v0 + v1; s2[t] = v0*v0 + v1*v1;
    __syncthreads();
    for (int st = 128; st > 0; st >>= 1) { if (t < st) { s1[t] += s1[t+st]; s2[t] += s2[t+st]; } __syncthreads(); }
    float mu  = s1[0] * (1.f / D_);
    float var = s2[0] * (1.f / D_) - mu*mu;
    float inv = rsqrtf(var + 1e-5f);
    out[row*D_ + t]       = (v0 - mu) * inv * g[t]       + bta[t];
    out[row*D_ + t + 256] = (v1 - mu) * inv * g[t + 256] + bta[t + 256];
}

__global__ void pack_convw_k(const float* __restrict__ w)
{
    int idx = blockIdx.x * blockDim.x + threadIdx.x;
    if (idx >= (4*D_)*D_) return;
    int o = idx % D_;
    int kap = idx / D_;
    int r = kap / D_, d = kap % D_;
    g_packw[(long)kap*D_ + o] = w[(long)o*(D_*4) + d*4 + r];
}

__global__ void zero_loss_k() { if (threadIdx.x == 0 && blockIdx.x == 0) g_loss[0] = 0.f; }

__global__ void sse_k(const float* __restrict__ a, const float* __restrict__ b, int n)
{
    __shared__ float red[256];
    int t = threadIdx.x;
    float s = 0.f;
    for (int i = blockIdx.x * 256 + t; i < n; i += gridDim.x * 256) {
        float d = a[i] - b[i];
        s += d * d;
    }
    red[t] = s; __syncthreads();
    for (int st = 128; st > 0; st >>= 1) { if (t < st) red[t] += red[t+st]; __syncthreads(); }
    if (t == 0) atomicAdd(&g_loss[0], red[0]);
}

__global__ void finalize_k(float* __restrict__ out, int out_size)
{
    int idx = blockIdx.x * blockDim.x + threadIdx.x;
    if (idx >= out_size) return;
    const int n = B_*S_*D_;
    if (idx < n) out[idx] = g_x[idx];
    else         out[idx] = g_loss[0] * (1.f / ((float)n * (float)NL_));
}

// ------------------------------- host driver --------------------------------
static void gT(cudaStream_t st, bool tb, bool gelu,
               const float* A, const float* Bm, float* C, const float* bias,
               const float* Res, int M, int N, int K,
               int lda, int ldb, int ldc, float alpha,
               int batch = 1, int Hdiv = 1,
               long sAb = 0, long sAh = 0, long sBb = 0, long sBh = 0,
               long sCb = 0, long sCh = 0)
{
    dim3 g(N / 64, M / 64, batch);
    if (tb)
        gemm_t<true,false><<<g,128,0,st>>>(A,Bm,C,bias,Res,K,lda,ldb,ldc,alpha,Hdiv,sAb,sAh,sBb,sBh,sCb,sCh);
    else if (gelu)
        gemm_t<false,true><<<g,128,0,st>>>(A,Bm,C,bias,Res,K,lda,ldb,ldc,alpha,Hdiv,sAb,sAh,sBb,sBh,sCb,sCh);
    else
        gemm_t<false,false><<<g,128,0,st>>>(A,Bm,C,bias,Res,K,lda,ldb,ldc,alpha,Hdiv,sAb,sAh,sBb,sBh,sCb,sCh);
}

static float* dptr(const void* sym) { void* p = nullptr; cudaGetSymbolAddress(&p, sym); return (float*)p; }

extern "C" void kernel_launch(void* const* d_in, const int* in_sizes, int n_in,
                              void* d_out, int out_size)
{
    const int*   trg     = (const int*)  d_in[0];
    const float* latent  = (const float*)d_in[3];
    const float* mems    = (const float*)d_in[4];
    const float* cmems   = (const float*)d_in[5];
    const float* pos_emb = (const float*)d_in[6];
    const float* embed   = (const float*)d_in[7];
    const float* W_self  = (const float*)d_in[8];
    const float* ln1_g   = (const float*)d_in[9];
    const float* ln1_b   = (const float*)d_in[10];
    const float* conv_w  = (const float*)d_in[11];
    const float* conv_b  = (const float*)d_in[12];
    const float* W_src   = (const float*)d_in[13];
    const float* ln2_g   = (const float*)d_in[14];
    const float* ln2_b   = (const float*)d_in[15];
    const float* w1      = (const float*)d_in[16];
    const float* b1      = (const float*)d_in[17];
    const float* w2      = (const float*)d_in[18];
    const float* b2      = (const float*)d_in[19];

    float* px    = dptr(g_x);     float* pa    = dptr(g_a);
    float* pkv   = dptr(g_kv);    float* pq    = dptr(g_q);
    float* pq2   = dptr(g_q2);    float* pkvp  = dptr(g_kvp);
    float* pdots = dptr(g_dots);  float* ppd   = dptr(g_pd);
    float* pctx  = dptr(g_ctx);   float* ppackw= dptr(g_packw);
    float* pnewcm= dptr(g_newcm);
    float* ptb   = dptr(g_tb);    float* pcb   = dptr(g_cb);
    float* plkv  = dptr(g_lkv);
    float* pd2   = dptr(g_d2);    float* pd3   = dptr(g_d3);
    float* pdx   = dptr(g_dx);
    float* pctxt = dptr(g_ctxt);  float* pctxc = dptr(g_ctxc);
    float* py    = dptr(g_y);     float* ph1   = dptr(g_h1);

    float* pk  = pkvp;
    float* pv  = pkvp + (long)B_*KV_*D_;
    float* pkt = ptb;
    float* pvt = ptb + (long)B_*MEM_*D_;
    float* pkc = pcb;
    float* pvc = pcb + (long)B_*CMEM_*D_;
    float* plk = plkv;
    float* plv = plkv + (long)B_*LLAT_*D_;

    const int DD = D_ * D_;
    const int NX = B_*S_*D_;

    cudaStream_t s0 = (cudaStream_t)0;
    cudaStream_t s1;
    cudaStreamCreateWithFlags(&s1, cudaStreamNonBlocking);

    cudaEvent_t evX[NL_], eq[NL_], epos[NL_], eln[NL_], eq2[NL_], evLoss;
    for (int l = 0; l < NL_; l++) {
        cudaEventCreateWithFlags(&evX[l],  cudaEventDisableTiming);
        cudaEventCreateWithFlags(&eq[l],   cudaEventDisableTiming);
        cudaEventCreateWithFlags(&epos[l], cudaEventDisableTiming);
        cudaEventCreateWithFlags(&eln[l],  cudaEventDisableTiming);
        cudaEventCreateWithFlags(&eq2[l],  cudaEventDisableTiming);
    }
    cudaEventCreateWithFlags(&evLoss, cudaEventDisableTiming);

    embed_k<<<(NX + 255)/256, 256, 0, s0>>>(trg, embed);
    zero_loss_k<<<1, 32, 0, s0>>>();
    cudaEventRecord(evX[0], s0);

    for (int i = 0; i < NL_; i++) {
        const float* Wq  = W_self + (long)i*4*DD;
        const float* Wk  = Wq + DD;
        const float* Wo  = Wq + 3*DD;
        const float* Ws0 = W_src + (long)i*4*DD;
        const float* Ws1 = Ws0 + DD;
        const float* Ws3 = Ws0 + 3*DD;
        const float* mems_i  = mems  + (long)i*B_*MEM_*D_;
        const float* cmems_i = cmems + (long)i*B_*CMEM_*D_;
        const float* convw_i = conv_w + (long)i*DD*4;
        const float* convb_i = conv_b + (long)i*D_;
        const float* w1_i = w1 + (long)i*D_*FF_;
        const float* b1_i = b1 + (long)i*FF_;
        const float* w2_i = w2 + (long)i*FF_*D_;
        const float* b2_i = b2 + (long)i*D_;

        // ========= stream 1: Q proj, pos dots, then mem-side recon prep =====
        cudaStreamWaitEvent(s1, evX[i], 0);
        gT(s1, false,false, px, Wq, pq, nullptr, nullptr, B_*S_, D_, D_, D_, D_, D_, 1.f);
        cudaEventRecord(eq[i], s1);
        gT(s1, true,false, pq, pos_emb, ppd, nullptr, nullptr, S_, KV_, DH_, D_, DH_, KV_, 8.f,
           B_*H_, H_, (long)S_*D_, 64, 0, (long)KV_*DH_, (long)H_*S_*KV_, (long)S_*KV_);
        cudaEventRecord(epos[i], s1);
        pack_convw_k<<<((4*D_)*D_ + 255)/256, 256, 0, s1>>>(convw_i);
        gT(s1, false,false, mems_i, ppackw, pnewcm, convb_i, nullptr, B_*CMEM_, D_, 4*D_, 4*D_, D_, D_, 1.f);
        gT(s1, false,false, mems_i, Wk, pkt, nullptr, nullptr, B_*MEM_, D_, D_, D_, D_, D_, 1.f,
           2, 1, 0, 0, DD, 0, (long)B_*MEM_*D_, 0);
        gT(s1, false,false, pnewcm, Wk, pkc, nullptr, nullptr, B_*CMEM_, D_, D_, D_, D_, D_, 1.f,
           2, 1, 0, 0, DD, 0, (long)B_*CMEM_*D_, 0);

        // ========= stream 0: self-attention ================================
        concat_kv_k<<<(B_*KV_*D_ + 255)/256, 256, 0, s0>>>(cmems_i, mems_i);
        gT(s0, false,false, pkv, Wk, pk, nullptr, nullptr, B_*KV_, D_, D_, D_, D_, D_, 1.f,
           2, 1, 0, 0, DD, 0, (long)B_*KV_*D_, 0);
        cudaStreamWaitEvent(s0, eq[i], 0);
        gT(s0, true,false, pq, pk, pdots, nullptr, nullptr, S_, KV_, DH_, D_, D_, KV_, 0.125f,
           B_*H_, H_, (long)S_*D_, 64, (long)KV_*D_, 64, (long)H_*S_*KV_, (long)S_*KV_);
        cudaStreamWaitEvent(s0, epos[i], 0);
        softmax_pos_k<<<B_*H_*S_, 256, 0, s0>>>();
        gT(s0, false,false, pdots, pv, pctx, nullptr, nullptr, S_, DH_, KV_, KV_, D_, D_, 1.f,
           B_*H_, H_, (long)H_*S_*KV_, (long)S_*KV_, (long)KV_*D_, 64, (long)S_*D_, 64);
        gT(s0, false,false, pctx, Wo, pa, nullptr, nullptr, B_*S_, D_, D_, D_, D_, D_, 1.f);
        ln_k<<<B_*S_, 256, 0, s0>>>(pa, px, px, ln1_g + (long)i*D_, ln1_b + (long)i*D_);
        cudaEventRecord(eln[i], s0);

        // ========= stream 1: reconstruction attentions + loss ===============
        cudaStreamWaitEvent(s1, eln[i], 0);
        gT(s1, false,false, px, Wq, pq2, nullptr, nullptr, B_*S_, D_, D_, D_, D_, D_, 1.f);
        cudaEventRecord(eq2[i], s1);
        gT(s1, true,false, pq2, pkt, pd2, nullptr, nullptr, S_, MEM_, DH_, D_, D_, MEM_, 0.125f,
           B_*H_, H_, (long)S_*D_, 64, (long)MEM_*D_, 64, (long)H_*S_*MEM_, (long)S_*MEM_);
        softmax_k<<<B_*H_*S_, 256, 0, s1>>>(pd2, MEM_);
        gT(s1, false,false, pd2, pvt, pctxt, nullptr, nullptr, S_, DH_, MEM_, MEM_, D_, D_, 1.f,
           B_*H_, H_, (long)H_*S_*MEM_, (long)S_*MEM_, (long)MEM_*D_, 64, (long)S_*D_, 64);
        gT(s1, true,false, pq2, pkc, pd3, nullptr, nullptr, S_, CMEM_, DH_, D_, D_, CMEM_, 0.125f,
           B_*H_, H_, (long)S_*D_, 64, (long)CMEM_*D_, 64, (long)H_*S_*CMEM_, (long)S_*CMEM_);
        softmax_k<<<B_*H_*S_, 256, 0, s1>>>(pd3, CMEM_);
        gT(s1, false,false, pd3, pvc, pctxc, nullptr, nullptr, S_, DH_, CMEM_, CMEM_, D_, D_, 1.f,
           B_*H_, H_, (long)H_*S_*CMEM_, (long)S_*CMEM_, (long)CMEM_*D_, 64, (long)S_*D_, 64);
        sse_k<<<1024, 256, 0, s1>>>(pctxc, pctxt, NX);
        if (i == NL_ - 1) cudaEventRecord(evLoss, s1);

        // ========= stream 0: cross attention + FFN ==========================
        gT(s0, false,false, px,     Ws0, pq,  nullptr, nullptr, B_*S_, D_, D_, D_, D_, D_, 1.f);
        gT(s0, false,false, latent, Ws1, plk, nullptr, nullptr, B_*LLAT_, D_, D_, D_, D_, D_, 1.f,
           2, 1, 0, 0, DD, 0, (long)B_*LLAT_*D_, 0);
        gT(s0, true,false, pq, plk, pdx, nullptr, nullptr, S_, LLAT_, DH_, D_, D_, LLAT_, 0.125f,
           B_*H_, H_, (long)S_*D_, 64, (long)LLAT_*D_, 64, (long)H_*S_*LLAT_, (long)S_*LLAT_);
        softmax_k<<<B_*H_*S_, 256, 0, s0>>>(pdx, LLAT_);
        gT(s0, false,false, pdx, plv, pctx, nullptr, nullptr, S_, DH_, LLAT_, LLAT_, D_, D_, 1.f,
           B_*H_, H_, (long)H_*S_*LLAT_, (long)S_*LLAT_, (long)LLAT_*D_, 64, (long)S_*D_, 64);
        gT(s0, false,false, pctx, Ws3, pa, nullptr, nullptr, B_*S_, D_, D_, D_, D_, D_, 1.f);

        ln_k<<<B_*S_, 256, 0, s0>>>(pa, nullptr, py, ln2_g + (long)i*D_, ln2_b + (long)i*D_);
        gT(s0, false,true,  py, w1_i, ph1, b1_i, nullptr, B_*S_, FF_, D_, D_, FF_, FF_, 1.f);
        cudaStreamWaitEvent(s0, eq2[i], 0);
        gT(s0, false,false, ph1, w2_i, px, b2_i, pa, B_*S_, D_, FF_, FF_, D_, D_, 1.f);
        if (i + 1 < NL_) cudaEventRecord(evX[i+1], s0);
    }

    cudaStreamWaitEvent(s0, evLoss, 0);
    finalize_k<<<(out_size + 255)/256, 256, 0, s0>>>((float*)d_out, out_size);

    cudaStreamCaptureStatus cst = cudaStreamCaptureStatusNone;
    cudaStreamIsCapturing(s0, &cst);
    if (cst == cudaStreamCaptureStatusNone) {
        for (int l = 0; l < NL_; l++) {
            cudaEventDestroy(evX[l]); cudaEventDestroy(eq[l]); cudaEventDestroy(epos[l]);
            cudaEventDestroy(eln[l]); cudaEventDestroy(eq2[l]);
        }
        cudaEventDestroy(evLoss);
        cudaStreamDestroy(s1);
    }
}

// round 14
// speedup vs baseline: 1.0105x; 1.0105x over previous
#include <cuda_runtime.h>
#include <math.h>
#include <stdint.h>

#define B_    4
#define S_    512
#define D_    512
#define H_    8
#define DH_   64
#define MEM_  512
#define CMEM_ 128
#define KV_   1152
#define LLAT_ 256
#define FF_   2048
#define NL_   4

// ------------------------- scratch (device globals) -------------------------
__device__ float g_x   [B_*S_*D_];
__device__ float g_a   [B_*S_*D_];
__device__ float g_kv  [B_*KV_*D_];
__device__ float g_q   [B_*S_*D_];
__device__ float g_q2  [B_*S_*D_];
__device__ float g_kvp [2*B_*KV_*D_];
__device__ float g_dots[B_*H_*S_*KV_];
__device__ float g_pd  [B_*H_*S_*KV_];
__device__ float g_ctx [B_*S_*D_];
__device__ float g_packw[(4*D_)*D_];
__device__ float g_newcm[B_*CMEM_*D_];
__device__ float g_tb  [2*B_*MEM_*D_];
__device__ float g_cb  [2*B_*CMEM_*D_];
__device__ float g_lkv [2*B_*LLAT_*D_];
__device__ float g_d2  [B_*H_*S_*MEM_];
__device__ float g_d3  [B_*H_*S_*CMEM_];
__device__ float g_dx  [B_*H_*S_*LLAT_];
__device__ float g_ctxt[B_*S_*D_];
__device__ float g_ctxc[B_*S_*D_];
__device__ float g_y   [B_*S_*D_];
__device__ float g_h1  [B_*S_*FF_];
__device__ float g_loss[1];

// ------------------------- TF32 helpers -------------------------------------
__device__ __forceinline__ uint32_t f2tf(float x) {
    uint32_t r;
    asm("cvt.rna.tf32.f32 %0, %1;" : "=r"(r) : "f"(x));
    return r;
}
__device__ __forceinline__ void split3(float x, float& h, float& l) {
    uint32_t u = f2tf(x);
    h = __uint_as_float(u);
    l = __uint_as_float(f2tf(x - h));
}

__device__ __forceinline__ void mma8(float c[4], const uint32_t a[4], const uint32_t b[2]) {
    asm volatile(
        "mma.sync.aligned.m16n8k8.row.col.f32.tf32.tf32.f32 "
        "{%0,%1,%2,%3},{%4,%5,%6,%7},{%8,%9},{%0,%1,%2,%3};\n"
        : "+f"(c[0]), "+f"(c[1]), "+f"(c[2]), "+f"(c[3])
        : "r"(a[0]), "r"(a[1]), "r"(a[2]), "r"(a[3]), "r"(b[0]), "r"(b[1]));
}

// ------------------------- 3xTF32 tensor-core GEMM --------------------------
// Identical math/layout to R4/R6; producers rewritten for conflict-free STS.128.
// smem layout: [plane hi/lo][row m or n (64)][k (32, padded to 36)].
// Row stride 36 floats = 144 B (16B-aligned); STS.128 per-phase bank-groups
// (m + k/4) mod 8 are distinct -> conflict-free.
#define SST 36
template<bool TB, bool GELU>
__global__ void __launch_bounds__(128) gemm_t(
    const float* __restrict__ A, const float* __restrict__ Bm,
    float* __restrict__ C, const float* __restrict__ bias,
    const float* __restrict__ Res,
    int K, int lda, int ldb, int ldc, float alpha,
    int Hdiv, long sAb, long sAh, long sBb, long sBh, long sCb, long sCh)
{
    const int z  = blockIdx.z;
    const int bi = z / Hdiv, hi = z - bi * Hdiv;
    A  += (long)bi*sAb + (long)hi*sAh;
    Bm += (long)bi*sBb + (long)hi*sBh;
    C  += (long)bi*sCb + (long)hi*sCh;

    const int m0 = blockIdx.y * 64;
    const int n0 = blockIdx.x * 64;

    __shared__ __align__(16) float As[2][64][SST];
    __shared__ __align__(16) float Bs[2][64][SST];

    const int t    = threadIdx.x;
    const int warp = t >> 5;
    const int lane = t & 31;
    const int wm = (warp & 1) * 32;
    const int wn = (warp >> 1) * 32;
    const int group = lane >> 2;
    const int tig   = lane & 3;

    float c[2][4][4];
#pragma unroll
    for (int mt = 0; mt < 2; mt++)
#pragma unroll
        for (int nt = 0; nt < 4; nt++)
#pragma unroll
            for (int r = 0; r < 4; r++) c[mt][nt][r] = 0.f;

    for (int k0 = 0; k0 < K; k0 += 32) {
        // ---- A tile: float4 load, split, two STS.128 (conflict-free) ----
#pragma unroll
        for (int p = 0; p < 4; p++) {
            const int m = (t >> 3) + p * 16;
            const int k = (t & 7) << 2;
            float4 v = *(const float4*)(A + (long)(m0 + m) * lda + k0 + k);
            float4 h, l;
            split3(v.x, h.x, l.x); split3(v.y, h.y, l.y);
            split3(v.z, h.z, l.z); split3(v.w, h.w, l.w);
            *(float4*)&As[0][m][k] = h;
            *(float4*)&As[1][m][k] = l;
        }
        if (TB) {
            // B is [N,K] row-major: same pattern as A
#pragma unroll
            for (int p = 0; p < 4; p++) {
                const int n = (t >> 3) + p * 16;
                const int k = (t & 7) << 2;
                float4 v = *(const float4*)(Bm + (long)(n0 + n) * ldb + k0 + k);
                float4 h, l;
                split3(v.x, h.x, l.x); split3(v.y, h.y, l.y);
                split3(v.z, h.z, l.z); split3(v.w, h.w, l.w);
                *(float4*)&Bs[0][n][k] = h;
                *(float4*)&Bs[1][n][k] = l;
            }
        } else {
            // B is [K,N] row-major: 16 coalesced LDG.32 along k per thread
            // (lanes walk n), then STS.128 along the thread's own [n][k] row.
            const int n  = t & 63;
            const int kb = (t >> 6) << 4;     // 0 or 16
            const float* bp = Bm + (long)(k0 + kb) * ldb + n0 + n;
            float v[16];
#pragma unroll
            for (int i = 0; i < 16; i++) v[i] = bp[(long)i * ldb];
#pragma unroll
            for (int q = 0; q < 4; q++) {
                float4 h, l;
                split3(v[4*q+0], h.x, l.x); split3(v[4*q+1], h.y, l.y);
                split3(v[4*q+2], h.z, l.z); split3(v[4*q+3], h.w, l.w);
                *(float4*)&Bs[0][n][kb + 4*q] = h;
                *(float4*)&Bs[1][n][kb + 4*q] = l;
            }
        }
        __syncthreads();

#pragma unroll
        for (int kk = 0; kk < 32; kk += 8) {
            uint32_t ah[2][4], al[2][4], bh[4][2], bl[4][2];
#pragma unroll
            for (int mt = 0; mt < 2; mt++) {
                const int r0 = wm + mt * 16 + group;
                ah[mt][0] = __float_as_uint(As[0][r0    ][kk + tig]);
                ah[mt][1] = __float_as_uint(As[0][r0 + 8][kk + tig]);
                ah[mt][2] = __float_as_uint(As[0][r0    ][kk + tig + 4]);
                ah[mt][3] = __float_as_uint(As[0][r0 + 8][kk + tig + 4]);
                al[mt][0] = __float_as_uint(As[1][r0    ][kk + tig]);
                al[mt][1] = __float_as_uint(As[1][r0 + 8][kk + tig]);
                al[mt][2] = __float_as_uint(As[1][r0    ][kk + tig + 4]);
                al[mt][3] = __float_as_uint(As[1][r0 + 8][kk + tig + 4]);
            }
#pragma unroll
            for (int nt = 0; nt < 4; nt++) {
                const int nr = wn + nt * 8 + group;
                bh[nt][0] = __float_as_uint(Bs[0][nr][kk + tig]);
                bh[nt][1] = __float_as_uint(Bs[0][nr][kk + tig + 4]);
                bl[nt][0] = __float_as_uint(Bs[1][nr][kk + tig]);
                bl[nt][1] = __float_as_uint(Bs[1][nr][kk + tig + 4]);
            }
#pragma unroll
            for (int mt = 0; mt < 2; mt++)
#pragma unroll
                for (int nt = 0; nt < 4; nt++) {
                    mma8(c[mt][nt], al[mt], bh[nt]);
                    mma8(c[mt][nt], ah[mt], bl[nt]);
                    mma8(c[mt][nt], ah[mt], bh[nt]);
                }
        }
        __syncthreads();
    }

#pragma unroll
    for (int mt = 0; mt < 2; mt++) {
#pragma unroll
        for (int half = 0; half < 2; half++) {
            const int gm = m0 + wm + mt * 16 + group + half * 8;
            float* crow = C + (long)gm * ldc;
            const float* rrow = Res ? (Res + (long)gm * ldc) : nullptr;
#pragma unroll
            for (int nt = 0; nt < 4; nt++) {
                const int gn = n0 + wn + nt * 8 + 2 * tig;
                float v0 = alpha * c[mt][nt][half * 2 + 0];
                float v1 = alpha * c[mt][nt][half * 2 + 1];
                if (bias) {
                    float2 bv = *(const float2*)&bias[gn];
                    v0 += bv.x; v1 += bv.y;
                }
                if (GELU) {
                    v0 = 0.5f * v0 * (1.f + erff(v0 * 0.70710678118654752f));
                    v1 = 0.5f * v1 * (1.f + erff(v1 * 0.70710678118654752f));
                }
                if (rrow) {
                    float2 rv = *(const float2*)&rrow[gn];
                    v0 += rv.x; v1 += rv.y;
                }
                *(float2*)&crow[gn] = make_float2(v0, v1);
            }
        }
    }
}

// ------------------------- elementwise / reduction kernels ------------------
__global__ void embed_k(const int* __restrict__ trg, const float* __restrict__ embed)
{
    int idx = blockIdx.x * blockDim.x + threadIdx.x;
    if (idx >= B_*S_*D_) return;
    int row = idx / D_;
    g_x[idx] = embed[(long)trg[row]*D_ + (idx % D_)];
}

__global__ void concat_kv_k(const float* __restrict__ cm, const float* __restrict__ m)
{
    int idx = blockIdx.x * blockDim.x + threadIdx.x;
    if (idx >= B_*KV_*D_) return;
    int d = idx % D_;
    int j = (idx / D_) % KV_;
    int b = idx / (D_*KV_);
    float v;
    if (j < CMEM_)             v = cm [((long)b*CMEM_ + j)*D_ + d];
    else if (j < CMEM_ + MEM_) v = m  [((long)b*MEM_ + (j - CMEM_))*D_ + d];
    else                       v = g_x[((long)b*S_  + (j - CMEM_ - MEM_))*D_ + d];
    g_kv[idx] = v;
}

__global__ void softmax_pos_k()
{
    const long row = blockIdx.x;
    const int  q   = (int)(row % S_);
    float* dp = g_dots + row * (long)KV_;
    const float* pp = g_pd + row * (long)KV_;
    const int t = threadIdx.x;

    float v[5];
    float m = -1e30f;
#pragma unroll
    for (int r = 0; r < 5; r++) {
        int i = t + 256*r;
        if (i < KV_) {
            float val = dp[i];
            int p = i - q + (S_ - 1);
            if (p < KV_) val += pp[p];
            v[r] = val;
            m = fmaxf(m, val);
        } else v[r] = -1e30f;
    }
    __shared__ float red[256];
    red[t] = m; __syncthreads();
    for (int st = 128; st > 0; st >>= 1) { if (t < st) red[t] = fmaxf(red[t], red[t+st]); __syncthreads(); }
    m = red[0]; __syncthreads();
    float s = 0.f;
#pragma unroll
    for (int r = 0; r < 5; r++) {
        int i = t + 256*r;
        if (i < KV_) { v[r] = expf(v[r] - m); s += v[r]; }
    }
    red[t] = s; __syncthreads();
    for (int st = 128; st > 0; st >>= 1) { if (t < st) red[t] += red[t+st]; __syncthreads(); }
    float inv = 1.f / red[0];
#pragma unroll
    for (int r = 0; r < 5; r++) {
        int i = t + 256*r;
        if (i < KV_) dp[i] = v[r] * inv;
    }
}

__global__ void softmax_k(float* __restrict__ d, int L)
{
    long row = blockIdx.x;
    float* p = d + row * (long)L;
    const int t = threadIdx.x;
    float v[5];
    float m = -1e30f;
    const int nr = (L + 255) >> 8;
    for (int r = 0; r < nr; r++) {
        int i = t + 256*r;
        v[r] = (i < L) ? p[i] : -1e30f;
        m = fmaxf(m, v[r]);
    }
    __shared__ float red[256];
    red[t] = m; __syncthreads();
    for (int st = 128; st > 0; st >>= 1) { if (t < st) red[t] = fmaxf(red[t], red[t+st]); __syncthreads(); }
    m = red[0]; __syncthreads();
    float s = 0.f;
    for (int r = 0; r < nr; r++) {
        int i = t + 256*r;
        if (i < L) { v[r] = expf(v[r] - m); s += v[r]; }
    }
    red[t] = s; __syncthreads();
    for (int st = 128; st > 0; st >>= 1) { if (t < st) red[t] += red[t+st]; __syncthreads(); }
    float inv = 1.f / red[0];
    for (int r = 0; r < nr; r++) {
        int i = t + 256*r;
        if (i < L) p[i] = v[r] * inv;
    }
}

__global__ void ln_k(const float* __restrict__ in, const float* __restrict__ res,
                     float* __restrict__ out, const float* __restrict__ g,
                     const float* __restrict__ bta)
{
    long row = blockIdx.x;
    const float* p = in + row * D_;
    int t = threadIdx.x;
    float v0 = p[t]       + (res ? res[row*D_ + t]       : 0.f);
    float v1 = p[t + 256] + (res ? res[row*D_ + t + 256] : 0.f);
    __shared__ float s1[256], s2[256];
    s1[t] = v0 + v1; s2[t] = v0*v0 + v1*v1;
    __syncthreads();
    for (int st = 128; st > 0; st >>= 1) { if (t < st) { s1[t] += s1[t+st]; s2[t] += s2[t+st]; } __syncthreads(); }
    float mu  = s1[0] * (1.f / D_);
    float var = s2[0] * (1.f / D_) - mu*mu;
    float inv = rsqrtf(var + 1e-5f);
    out[row*D_ + t]       = (v0 - mu) * inv * g[t]       + bta[t];
    out[row*D_ + t + 256] = (v1 - mu) * inv * g[t + 256] + bta[t + 256];
}

__global__ void pack_convw_k(const float* __restrict__ w)
{
    int idx = blockIdx.x * blockDim.x + threadIdx.x;
    if (idx >= (4*D_)*D_) return;
    int o = idx % D_;
    int kap = idx / D_;
    int r = kap / D_, d = kap % D_;
    g_packw[(long)kap*D_ + o] = w[(long)o*(D_*4) + d*4 + r];
}

__global__ void zero_loss_k() { if (threadIdx.x == 0 && blockIdx.x == 0) g_loss[0] = 0.f; }

__global__ void sse_k(const float* __restrict__ a, const float* __restrict__ b, int n)
{
    __shared__ float red[256];
    int t = threadIdx.x;
    float s = 0.f;
    for (int i = blockIdx.x * 256 + t; i < n; i += gridDim.x * 256) {
        float d = a[i] - b[i];
        s += d * d;
    }
    red[t] = s; __syncthreads();
    for (int st = 128; st > 0; st >>= 1) { if (t < st) red[t] += red[t+st]; __syncthreads(); }
    if (t == 0) atomicAdd(&g_loss[0], red[0]);
}

__global__ void finalize_k(float* __restrict__ out, int out_size)
{
    int idx = blockIdx.x * blockDim.x + threadIdx.x;
    if (idx >= out_size) return;
    const int n = B_*S_*D_;
    if (idx < n) out[idx] = g_x[idx];
    else         out[idx] = g_loss[0] * (1.f / ((float)n * (float)NL_));
}

// ------------------------------- host driver --------------------------------
static void gT(cudaStream_t st, bool tb, bool gelu,
               const float* A, const float* Bm, float* C, const float* bias,
               const float* Res, int M, int N, int K,
               int lda, int ldb, int ldc, float alpha,
               int batch = 1, int Hdiv = 1,
               long sAb = 0, long sAh = 0, long sBb = 0, long sBh = 0,
               long sCb = 0, long sCh = 0)
{
    dim3 g(N / 64, M / 64, batch);
    if (tb)
        gemm_t<true,false><<<g,128,0,st>>>(A,Bm,C,bias,Res,K,lda,ldb,ldc,alpha,Hdiv,sAb,sAh,sBb,sBh,sCb,sCh);
    else if (gelu)
        gemm_t<false,true><<<g,128,0,st>>>(A,Bm,C,bias,Res,K,lda,ldb,ldc,alpha,Hdiv,sAb,sAh,sBb,sBh,sCb,sCh);
    else
        gemm_t<false,false><<<g,128,0,st>>>(A,Bm,C,bias,Res,K,lda,ldb,ldc,alpha,Hdiv,sAb,sAh,sBb,sBh,sCb,sCh);
}

static float* dptr(const void* sym) { void* p = nullptr; cudaGetSymbolAddress(&p, sym); return (float*)p; }

extern "C" void kernel_launch(void* const* d_in, const int* in_sizes, int n_in,
                              void* d_out, int out_size)
{
    const int*   trg     = (const int*)  d_in[0];
    const float* latent  = (const float*)d_in[3];
    const float* mems    = (const float*)d_in[4];
    const float* cmems   = (const float*)d_in[5];
    const float* pos_emb = (const float*)d_in[6];
    const float* embed   = (const float*)d_in[7];
    const float* W_self  = (const float*)d_in[8];
    const float* ln1_g   = (const float*)d_in[9];
    const float* ln1_b   = (const float*)d_in[10];
    const float* conv_w  = (const float*)d_in[11];
    const float* conv_b  = (const float*)d_in[12];
    const float* W_src   = (const float*)d_in[13];
    const float* ln2_g   = (const float*)d_in[14];
    const float* ln2_b   = (const float*)d_in[15];
    const float* w1      = (const float*)d_in[16];
    const float* b1      = (const float*)d_in[17];
    const float* w2      = (const float*)d_in[18];
    const float* b2      = (const float*)d_in[19];

    float* px    = dptr(g_x);     float* pa    = dptr(g_a);
    float* pkv   = dptr(g_kv);    float* pq    = dptr(g_q);
    float* pq2   = dptr(g_q2);    float* pkvp  = dptr(g_kvp);
    float* pdots = dptr(g_dots);  float* ppd   = dptr(g_pd);
    float* pctx  = dptr(g_ctx);   float* ppackw= dptr(g_packw);
    float* pnewcm= dptr(g_newcm);
    float* ptb   = dptr(g_tb);    float* pcb   = dptr(g_cb);
    float* plkv  = dptr(g_lkv);
    float* pd2   = dptr(g_d2);    float* pd3   = dptr(g_d3);
    float* pdx   = dptr(g_dx);
    float* pctxt = dptr(g_ctxt);  float* pctxc = dptr(g_ctxc);
    float* py    = dptr(g_y);     float* ph1   = dptr(g_h1);

    float* pk  = pkvp;
    float* pv  = pkvp + (long)B_*KV_*D_;
    float* pkt = ptb;
    float* pvt = ptb + (long)B_*MEM_*D_;
    float* pkc = pcb;
    float* pvc = pcb + (long)B_*CMEM_*D_;
    float* plk = plkv;
    float* plv = plkv + (long)B_*LLAT_*D_;

    const int DD = D_ * D_;
    const int NX = B_*S_*D_;

    cudaStream_t s0 = (cudaStream_t)0;
    cudaStream_t s1;
    cudaStreamCreateWithFlags(&s1, cudaStreamNonBlocking);

    cudaEvent_t evX[NL_], eq[NL_], epos[NL_], eln[NL_], eq2[NL_], evLoss;
    for (int l = 0; l < NL_; l++) {
        cudaEventCreateWithFlags(&evX[l],  cudaEventDisableTiming);
        cudaEventCreateWithFlags(&eq[l],   cudaEventDisableTiming);
        cudaEventCreateWithFlags(&epos[l], cudaEventDisableTiming);
        cudaEventCreateWithFlags(&eln[l],  cudaEventDisableTiming);
        cudaEventCreateWithFlags(&eq2[l],  cudaEventDisableTiming);
    }
    cudaEventCreateWithFlags(&evLoss, cudaEventDisableTiming);

    embed_k<<<(NX + 255)/256, 256, 0, s0>>>(trg, embed);
    zero_loss_k<<<1, 32, 0, s0>>>();
    cudaEventRecord(evX[0], s0);

    for (int i = 0; i < NL_; i++) {
        const float* Wq  = W_self + (long)i*4*DD;
        const float* Wk  = Wq + DD;
        const float* Wo  = Wq + 3*DD;
        const float* Ws0 = W_src + (long)i*4*DD;
        const float* Ws1 = Ws0 + DD;
        const float* Ws3 = Ws0 + 3*DD;
        const float* mems_i  = mems  + (long)i*B_*MEM_*D_;
        const float* cmems_i = cmems + (long)i*B_*CMEM_*D_;
        const float* convw_i = conv_w + (long)i*DD*4;
        const float* convb_i = conv_b + (long)i*D_;
        const float* w1_i = w1 + (long)i*D_*FF_;
        const float* b1_i = b1 + (long)i*FF_;
        const float* w2_i = w2 + (long)i*FF_*D_;
        const float* b2_i = b2 + (long)i*D_;

        // ========= stream 1: Q proj, pos dots, then mem-side recon prep =====
        cudaStreamWaitEvent(s1, evX[i], 0);
        gT(s1, false,false, px, Wq, pq, nullptr, nullptr, B_*S_, D_, D_, D_, D_, D_, 1.f);
        cudaEventRecord(eq[i], s1);
        gT(s1, true,false, pq, pos_emb, ppd, nullptr, nullptr, S_, KV_, DH_, D_, DH_, KV_, 8.f,
           B_*H_, H_, (long)S_*D_, 64, 0, (long)KV_*DH_, (long)H_*S_*KV_, (long)S_*KV_);
        cudaEventRecord(epos[i], s1);
        pack_convw_k<<<((4*D_)*D_ + 255)/256, 256, 0, s1>>>(convw_i);
        gT(s1, false,false, mems_i, ppackw, pnewcm, convb_i, nullptr, B_*CMEM_, D_, 4*D_, 4*D_, D_, D_, 1.f);
        gT(s1, false,false, mems_i, Wk, pkt, nullptr, nullptr, B_*MEM_, D_, D_, D_, D_, D_, 1.f,
           2, 1, 0, 0, DD, 0, (long)B_*MEM_*D_, 0);
        gT(s1, false,false, pnewcm, Wk, pkc, nullptr, nullptr, B_*CMEM_, D_, D_, D_, D_, D_, 1.f,
           2, 1, 0, 0, DD, 0, (long)B_*CMEM_*D_, 0);

        // ========= stream 0: self-attention ================================
        concat_kv_k<<<(B_*KV_*D_ + 255)/256, 256, 0, s0>>>(cmems_i, mems_i);
        gT(s0, false,false, pkv, Wk, pk, nullptr, nullptr, B_*KV_, D_, D_, D_, D_, D_, 1.f,
           2, 1, 0, 0, DD, 0, (long)B_*KV_*D_, 0);
        cudaStreamWaitEvent(s0, eq[i], 0);
        gT(s0, true,false, pq, pk, pdots, nullptr, nullptr, S_, KV_, DH_, D_, D_, KV_, 0.125f,
           B_*H_, H_, (long)S_*D_, 64, (long)KV_*D_, 64, (long)H_*S_*KV_, (long)S_*KV_);
        cudaStreamWaitEvent(s0, epos[i], 0);
        softmax_pos_k<<<B_*H_*S_, 256, 0, s0>>>();
        gT(s0, false,false, pdots, pv, pctx, nullptr, nullptr, S_, DH_, KV_, KV_, D_, D_, 1.f,
           B_*H_, H_, (long)H_*S_*KV_, (long)S_*KV_, (long)KV_*D_, 64, (long)S_*D_, 64);
        gT(s0, false,false, pctx, Wo, pa, nullptr, nullptr, B_*S_, D_, D_, D_, D_, D_, 1.f);
        ln_k<<<B_*S_, 256, 0, s0>>>(pa, px, px, ln1_g + (long)i*D_, ln1_b + (long)i*D_);
        cudaEventRecord(eln[i], s0);

        // ========= stream 1: reconstruction attentions + loss ===============
        cudaStreamWaitEvent(s1, eln[i], 0);
        gT(s1, false,false, px, Wq, pq2, nullptr, nullptr, B_*S_, D_, D_, D_, D_, D_, 1.f);
        cudaEventRecord(eq2[i], s1);
        gT(s1, true,false, pq2, pkt, pd2, nullptr, nullptr, S_, MEM_, DH_, D_, D_, MEM_, 0.125f,
           B_*H_, H_, (long)S_*D_, 64, (long)MEM_*D_, 64, (long)H_*S_*MEM_, (long)S_*MEM_);
        softmax_k<<<B_*H_*S_, 256, 0, s1>>>(pd2, MEM_);
        gT(s1, false,false, pd2, pvt, pctxt, nullptr, nullptr, S_, DH_, MEM_, MEM_, D_, D_, 1.f,
           B_*H_, H_, (long)H_*S_*MEM_, (long)S_*MEM_, (long)MEM_*D_, 64, (long)S_*D_, 64);
        gT(s1, true,false, pq2, pkc, pd3, nullptr, nullptr, S_, CMEM_, DH_, D_, D_, CMEM_, 0.125f,
           B_*H_, H_, (long)S_*D_, 64, (long)CMEM_*D_, 64, (long)H_*S_*CMEM_, (long)S_*CMEM_);
        softmax_k<<<B_*H_*S_, 256, 0, s1>>>(pd3, CMEM_);
        gT(s1, false,false, pd3, pvc, pctxc, nullptr, nullptr, S_, DH_, CMEM_, CMEM_, D_, D_, 1.f,
           B_*H_, H_, (long)H_*S_*CMEM_, (long)S_*CMEM_, (long)CMEM_*D_, 64, (long)S_*D_, 64);
        sse_k<<<1024, 256, 0, s1>>>(pctxc, pctxt, NX);
        if (i == NL_ - 1) cudaEventRecord(evLoss, s1);

        // ========= stream 0: cross attention + FFN ==========================
        gT(s0, false,false, px,     Ws0, pq,  nullptr, nullptr, B_*S_, D_, D_, D_, D_, D_, 1.f);
        gT(s0, false,false, latent, Ws1, plk, nullptr, nullptr, B_*LLAT_, D_, D_, D_, D_, D_, 1.f,
           2, 1, 0, 0, DD, 0, (long)B_*LLAT_*D_, 0);
        gT(s0, true,false, pq, plk, pdx, nullptr, nullptr, S_, LLAT_, DH_, D_, D_, LLAT_, 0.125f,
           B_*H_, H_, (long)S_*D_, 64, (long)LLAT_*D_, 64, (long)H_*S_*LLAT_, (long)S_*LLAT_);
        softmax_k<<<B_*H_*S_, 256, 0, s0>>>(pdx, LLAT_);
        gT(s0, false,false, pdx, plv, pctx, nullptr, nullptr, S_, DH_, LLAT_, LLAT_, D_, D_, 1.f,
           B_*H_, H_, (long)H_*S_*LLAT_, (long)S_*LLAT_, (long)LLAT_*D_, 64, (long)S_*D_, 64);
        gT(s0, false,false, pctx, Ws3, pa, nullptr, nullptr, B_*S_, D_, D_, D_, D_, D_, 1.f);

        ln_k<<<B_*S_, 256, 0, s0>>>(pa, nullptr, py, ln2_g + (long)i*D_, ln2_b + (long)i*D_);
        gT(s0, false,true,  py, w1_i, ph1, b1_i, nullptr, B_*S_, FF_, D_, D_, FF_, FF_, 1.f);
        cudaStreamWaitEvent(s0, eq2[i], 0);
        gT(s0, false,false, ph1, w2_i, px, b2_i, pa, B_*S_, D_, FF_, FF_, D_, D_, 1.f);
        if (i + 1 < NL_) cudaEventRecord(evX[i+1], s0);
    }

    cudaStreamWaitEvent(s0, evLoss, 0);
    finalize_k<<<(out_size + 255)/256, 256, 0, s0>>>((float*)d_out, out_size);

    cudaStreamCaptureStatus cst = cudaStreamCaptureStatusNone;
    cudaStreamIsCapturing(s0, &cst);
    if (cst == cudaStreamCaptureStatusNone) {
        for (int l = 0; l < NL_; l++) {
            cudaEventDestroy(evX[l]); cudaEventDestroy(eq[l]); cudaEventDestroy(epos[l]);
            cudaEventDestroy(eln[l]); cudaEventDestroy(eq2[l]);
        }
        cudaEventDestroy(evLoss);
        cudaStreamDestroy(s1);
    }
}